// round 6
// baseline (speedup 1.0000x reference)
#include <cuda_runtime.h>
#include <math.h>

#define BB 8
#define TT 1024
#define DD 128
#define UU 2048
#define OUTF (DD + UU)
#define NCTA 128
#define COLS 16
#define NTHR 1024
#define NWARP 32

typedef unsigned long long ull;

// SMEM layout (floats)
#define W_FLOATS   (UU * COLS)    // 32768  w_res slice [2048][16], 64B rows, chunk-swizzled
#define S_FLOATS   (UU * BB)      // 16384  state [2048][8], 16B-granule swizzled
#define WI_FLOATS  (DD * COLS)    // 2048   w_in slice, same swizzle as w
#define BI_FLOATS  16
#define RED_ULL    (NWARP * 16)   // [32 warps][16] f32x2 warp partials
#define SMEM_FLOATS (W_FLOATS + S_FLOATS + WI_FLOATS + BI_FLOATS + RED_ULL * 2)
#define SMEM_BYTES  (SMEM_FLOATS * 4)   // ~209 KB < 227 KB

__device__ float g_state[2][UU * BB];   // ping-pong state, linear [k][b]
__device__ unsigned g_bar_count;        // init-barrier
__device__ unsigned g_bar_gen;          // monotone across replays
__device__ unsigned g_step_count;       // per-step arrivals (64/CTA), reset each launch

__device__ __forceinline__ void cp16(unsigned dst, const void* src) {
    asm volatile("cp.async.cg.shared.global [%0], [%1], 16;" :: "r"(dst), "l"(src));
}
__device__ __forceinline__ void cp_commit() { asm volatile("cp.async.commit_group;"); }
template <int N>
__device__ __forceinline__ void cp_wait() {
    asm volatile("cp.async.wait_group %0;" :: "n"(N));
}
// packed fp32x2 ops — ptxas never emits these from C++
__device__ __forceinline__ void ffma2(ull& acc, ull a, ull b) {
    asm("fma.rn.f32x2 %0, %1, %2, %0;" : "+l"(acc) : "l"(a), "l"(b));
}
__device__ __forceinline__ ull dup2(float x) {
    ull r;
    unsigned xi = __float_as_uint(x);
    asm("mov.b64 %0, {%1, %1};" : "=l"(r) : "r"(xi));
    return r;
}
__device__ __forceinline__ ull padd2(ull a, ull b) {
    ull r;
    asm("add.rn.f32x2 %0, %1, %2;" : "=l"(r) : "l"(a), "l"(b));
    return r;
}
__device__ __forceinline__ ull bfly2(ull v, int m) {
    unsigned lo = (unsigned)v, hi = (unsigned)(v >> 32);
    lo = __shfl_xor_sync(0xffffffffu, lo, m);
    hi = __shfl_xor_sync(0xffffffffu, hi, m);
    ull r;
    asm("mov.b64 %0, {%1, %2};" : "=l"(r) : "r"(lo), "r"(hi));
    return r;
}

// init-only grid barrier (proven pattern)
__device__ __forceinline__ void grid_barrier_init() {
    __syncthreads();
    if (threadIdx.x == 0) {
        __threadfence();
        unsigned gen;
        asm volatile("ld.acquire.gpu.u32 %0, [%1];" : "=r"(gen) : "l"(&g_bar_gen));
        if (atomicAdd(&g_bar_count, 1) == NCTA - 1) {
            g_bar_count = 0;
            asm volatile("st.release.gpu.u32 [%0], %1;" :: "l"(&g_bar_gen), "r"(gen + 1)
                         : "memory");
        } else {
            unsigned cur;
            do {
                asm volatile("ld.acquire.gpu.u32 %0, [%1];" : "=r"(cur) : "l"(&g_bar_gen));
                if (cur != gen) break;
                __nanosleep(32);
            } while (true);
        }
    }
    __syncthreads();
}

__global__ void __launch_bounds__(NTHR, 1)
esn_kernel(const float* __restrict__ inputs, const float* __restrict__ w_in_g,
           const float* __restrict__ b_in_g, const float* __restrict__ w_res_g,
           float* __restrict__ out) {
    extern __shared__ float smem[];
    float* w_sh  = smem;                    // [2048][16]
    float* s_sh  = w_sh + W_FLOATS;         // [2048][8] swizzled
    float* wi_sh = s_sh + S_FLOATS;         // [128][16]
    float* bi_sh = wi_sh + WI_FLOATS;       // [16]
    ull* red = (ull*)(bi_sh + BI_FLOATS);   // [32 warps][16]

    const int tid = threadIdx.x;
    const int cta = blockIdx.x;
    const int col0 = cta * COLS;

    if (cta == 0 && tid == 0) g_step_count = 0;   // fresh epoch per launch/replay

    // Stage w_res slice; 16B chunk c of row r stored at position c ^ ((r>>1)&3)
    for (int r = tid; r < UU; r += NTHR) {
        const float4* src = (const float4*)(w_res_g + (size_t)r * UU + col0);
        int m = (r >> 1) & 3;
        float4* dst = (float4*)(w_sh + r * COLS);
        dst[0 ^ m] = src[0]; dst[1 ^ m] = src[1];
        dst[2 ^ m] = src[2]; dst[3 ^ m] = src[3];
    }
    if (tid < DD) {
        int r = tid;
        const float4* src = (const float4*)(w_in_g + (size_t)r * UU + col0);
        int m = (r >> 1) & 3;
        float4* dst = (float4*)(wi_sh + r * COLS);
        dst[0 ^ m] = src[0]; dst[1 ^ m] = src[1];
        dst[2 ^ m] = src[2]; dst[3 ^ m] = src[3];
    }
    if (tid < COLS) bi_sh[tid] = b_in_g[col0 + tid];

    // Zero initial state (buffer 0)
    for (int i = cta * NTHR + tid; i < UU * BB; i += NCTA * NTHR) g_state[0][i] = 0.0f;

    grid_barrier_init();

    // Decomposition: 256 k-slices x 2 col-halves x 2 batch-halves
    const int ks = tid & 255;
    const int bh = (tid >> 8) & 1;
    const int jh = tid >> 9;
    const int mk = (ks >> 1) & 3;            // weight swizzle key (thread-const)
    const unsigned w_off0 = (unsigned)(4 * ks + ((2 * jh) ^ mk)) * 16;
    const unsigned w_off1 = (unsigned)(4 * ks + ((2 * jh + 1) ^ mk)) * 16;
    const unsigned Gs = (unsigned)(2 * ks + bh);
    const unsigned s_off = (Gs ^ ((Gs >> 3) & 1)) * 16;   // state swizzle (thread-const)
    const int warp = tid >> 5;
    const int lane = tid & 31;
    const int brev = ((lane & 1) << 3) | ((lane & 2) << 1) |
                     ((lane & 4) >> 1) | ((lane & 8) >> 3);
    const unsigned s_base = (unsigned)__cvta_generic_to_shared(s_sh);

    for (int t = 0; t < TT; ++t) {
        // x_t (4 batches of this thread's bh-half); independent of state
        float xv[4];
        if (ks < DD) {
#pragma unroll
            for (int b = 0; b < 4; ++b)
                xv[b] = __ldg(inputs + ((size_t)((bh * 4 + b) * TT + t)) * DD + ks);
        }

        // Step gate: all 128 CTAs x 64 epilogue-releases for step t-1
        if (tid == 0) {
            const unsigned target = 8192u * (unsigned)t;
            unsigned v;
            do {
                asm volatile("ld.acquire.gpu.global.u32 %0, [%1];"
                             : "=r"(v) : "l"(&g_step_count));
            } while (v < target);
        }
        __syncthreads();

        // Broadcast state: 4 chunks x 16KB; granule g stored at g ^ ((g>>3)&1)
        const float* sg = g_state[t & 1];
#pragma unroll
        for (int c = 0; c < 4; ++c) {
            int g = c * 1024 + tid;
            cp16(s_base + ((unsigned)(g ^ ((g >> 3) & 1)) << 4), sg + g * 4);
            cp_commit();
        }

        ull acc[4][4];
#pragma unroll
        for (int a1 = 0; a1 < 4; ++a1)
#pragma unroll
            for (int a2 = 0; a2 < 4; ++a2) acc[a1][a2] = 0ULL;

        // Input projection (overlaps chunk-0 flight); wi has same swizzle as w
        if (ks < DD) {
            ulonglong2 u0 = *(const ulonglong2*)((const char*)wi_sh + w_off0);
            ulonglong2 u1 = *(const ulonglong2*)((const char*)wi_sh + w_off1);
#pragma unroll
            for (int b = 0; b < 4; ++b) {
                ull d = dup2(xv[b]);
                ffma2(acc[b][0], u0.x, d); ffma2(acc[b][1], u0.y, d);
                ffma2(acc[b][2], u1.x, d); ffma2(acc[b][3], u1.y, d);
            }
        }

#define ROW(i)                                                                        \
    {                                                                                 \
        float4 s = *(const float4*)((const char*)s_sh + s_off + (i) * 8192);          \
        ulonglong2 u0 = *(const ulonglong2*)((const char*)w_sh + w_off0 + (i) * 16384); \
        ulonglong2 u1 = *(const ulonglong2*)((const char*)w_sh + w_off1 + (i) * 16384); \
        ull d;                                                                        \
        d = dup2(s.x);                                                                \
        ffma2(acc[0][0], u0.x, d); ffma2(acc[0][1], u0.y, d);                         \
        ffma2(acc[0][2], u1.x, d); ffma2(acc[0][3], u1.y, d);                         \
        d = dup2(s.y);                                                                \
        ffma2(acc[1][0], u0.x, d); ffma2(acc[1][1], u0.y, d);                         \
        ffma2(acc[1][2], u1.x, d); ffma2(acc[1][3], u1.y, d);                         \
        d = dup2(s.z);                                                                \
        ffma2(acc[2][0], u0.x, d); ffma2(acc[2][1], u0.y, d);                         \
        ffma2(acc[2][2], u1.x, d); ffma2(acc[2][3], u1.y, d);                         \
        d = dup2(s.w);                                                                \
        ffma2(acc[3][0], u0.x, d); ffma2(acc[3][1], u0.y, d);                         \
        ffma2(acc[3][2], u1.x, d); ffma2(acc[3][3], u1.y, d);                         \
    }

        // Pipelined dot: chunk c holds rows 512c..512c+511 = i = 2c, 2c+1
        cp_wait<3>(); __syncthreads();
        ROW(0) ROW(1)
        cp_wait<2>(); __syncthreads();
        ROW(2) ROW(3)
        cp_wait<1>(); __syncthreads();
        ROW(4) ROW(5)
        cp_wait<0>(); __syncthreads();
        ROW(6) ROW(7)
#undef ROW

        // Warp butterfly: 16 accs/lane -> 1; lane L (<16) holds acc index brev4(L)
        {
            ull* A = &acc[0][0];
#pragma unroll
            for (int lev = 0; lev < 4; ++lev) {
                const int mm = 1 << lev;
                const int n = 8 >> lev;
                const bool up = (lane & mm) != 0;
#pragma unroll
                for (int q = 0; q < n; ++q) {
                    ull send = up ? A[q] : A[q + n];
                    ull recv = bfly2(send, mm);
                    ull keep = up ? A[q + n] : A[q];
                    A[q] = padd2(keep, recv);
                }
            }
            A[0] = padd2(A[0], bfly2(A[0], 16));
            if (lane < 16) red[warp * 16 + brev] = A[0];
        }
        __syncthreads();

        // Final reduce over 8 warps per (jh,bh) + epilogue (64 threads)
        if (tid < 64) {
            const int a = tid & 15;
            const int bh2 = (tid >> 4) & 1;
            const int jh2 = tid >> 5;
            const int wb = jh2 * 16 + bh2 * 8;
            ull v = red[wb * 16 + a];
#pragma unroll
            for (int w = 1; w < 8; ++w) v = padd2(v, red[(wb + w) * 16 + a]);
            const int b = bh2 * 4 + (a >> 2);
            const int jl = jh2 * 8 + (a & 3) * 2;
            const int c0 = col0 + jl;
            float pre0 = __uint_as_float((unsigned)v) + bi_sh[jl];
            float pre1 = __uint_as_float((unsigned)(v >> 32)) + bi_sh[jl + 1];
            // old state from swizzled SMEM
            unsigned G0 = (unsigned)(2 * c0 + (b >> 2));
            unsigned G1 = G0 + 2;
            float so0 = s_sh[(G0 ^ ((G0 >> 3) & 1)) * 4 + (b & 3)];
            float so1 = s_sh[(G1 ^ ((G1 >> 3) & 1)) * 4 + (b & 3)];
            float n0 = 0.5f * so0 + 0.5f * tanhf(pre0);
            float n1 = 0.5f * so1 + 0.5f * tanhf(pre1);
            float* sn = g_state[(t & 1) ^ 1];      // linear layout in global
            __stcg(sn + c0 * 8 + b, n0);
            __stcg(sn + (c0 + 1) * 8 + b, n1);
            float2 ov;                              // PowerIndex: even col squared
            ov.x = n0 * n0;
            ov.y = n1;
            *(float2*)(out + ((size_t)(b * TT + t)) * OUTF + DD + c0) = ov;
            // per-thread release: orders this thread's stores; 64 arrivals/CTA
            asm volatile("red.release.gpu.global.add.u32 [%0], %1;"
                         :: "l"(&g_step_count), "r"(1u) : "memory");
        }
    }
}

__global__ void copy_inputs_kernel(const float4* __restrict__ in, float* __restrict__ out) {
    int idx = blockIdx.x * blockDim.x + threadIdx.x;
    if (idx < BB * TT * DD / 4) {
        int bt = idx >> 5;  // 32 float4 per (b,t) row
        int q = idx & 31;
        float4 v = in[idx];
        *(float4*)(out + (size_t)bt * OUTF + q * 4) = v;
    }
}

extern "C" void kernel_launch(void* const* d_in, const int* in_sizes, int n_in,
                              void* d_out, int out_size) {
    const float* inputs = (const float*)d_in[0];
    const float* w_in   = (const float*)d_in[1];
    const float* b_in   = (const float*)d_in[2];
    const float* w_res  = (const float*)d_in[3];
    float* out = (float*)d_out;

    cudaFuncSetAttribute(esn_kernel, cudaFuncAttributeMaxDynamicSharedMemorySize, SMEM_BYTES);

    copy_inputs_kernel<<<(BB * TT * DD / 4 + 255) / 256, 256>>>((const float4*)inputs, out);
    esn_kernel<<<NCTA, NTHR, SMEM_BYTES>>>(inputs, w_in, b_in, w_res, out);
}